// round 12
// baseline (speedup 1.0000x reference)
#include <cuda_runtime.h>
#include <cuda_fp16.h>

#define D 128
#define NMAX 500000
#define BMAX 4096
#define XS_STRIDE 132   // padded floats per staged row (bank spread)
#define X2S_STRIDE 72   // halves per staged x2 row (144B; conflict-free STS)

// Scratch (static __device__ globals — no allocation anywhere)
__device__ __align__(16) __half g_x2h[(size_t)NMAX * D];  // 128 MB fp16 x2
__device__ float g_sums[BMAX * D];
__device__ float g_cnt[BMAX];
__device__ float g_tg[BMAX * D];
__device__ int   g_is64;

__device__ __forceinline__ float ftanh(float v) {
    float r;
    asm("tanh.approx.f32 %0,%1;" : "=f"(r) : "f"(v));
    return r;
}
__device__ __forceinline__ float fsigmoid(float v) {
    float r;
    asm("tanh.approx.f32 %0,%1;" : "=f"(r) : "f"(0.5f * v));
    return fmaf(0.5f, r, 0.5f);
}

__device__ __forceinline__ void cpa16(const void* smem_dst, const void* gmem_src) {
    unsigned s = (unsigned)__cvta_generic_to_shared(smem_dst);
    asm volatile("cp.async.cg.shared.global [%0],[%1],16;" :: "r"(s), "l"(gmem_src));
}
#define CP_COMMIT() asm volatile("cp.async.commit_group;")
#define CP_WAIT1()  asm volatile("cp.async.wait_group 1;")
#define CP_WAIT0()  asm volatile("cp.async.wait_group 0;")

// m16n8k16 row.col f32 += f16*f16
__device__ __forceinline__ void mma16816(float c[4], const unsigned a[4], const unsigned b[2]) {
    asm volatile(
        "mma.sync.aligned.m16n8k16.row.col.f32.f16.f16.f32 "
        "{%0,%1,%2,%3},{%4,%5,%6,%7},{%8,%9},{%0,%1,%2,%3};"
        : "+f"(c[0]), "+f"(c[1]), "+f"(c[2]), "+f"(c[3])
        : "r"(a[0]), "r"(a[1]), "r"(a[2]), "r"(a[3]), "r"(b[0]), "r"(b[1]));
}

__device__ __forceinline__ unsigned packh2(float a, float b) {
    __half2 h = __floats2half2_rn(a, b);
    return *(unsigned*)&h;
}
__device__ __forceinline__ float2 upkh2(unsigned u) {
    return __half22float2(*(__half2*)&u);
}

// ---------------------------------------------------------------------------
// K0: zero accumulators + output; detect batch element width (int64 vs int32).
// ---------------------------------------------------------------------------
__global__ void k_init(float* out, int outn, int B, const int* bw, int N) {
    int i = blockIdx.x * blockDim.x + threadIdx.x;
    int stride = gridDim.x * blockDim.x;
    for (int k = i; k < B * D; k += stride) g_sums[k] = 0.0f;
    for (int k = i; k < B; k += stride) g_cnt[k] = 0.0f;
    for (int k = i; k < outn; k += stride) out[k] = 0.0f;
    if (i == 0) {
        int io = N - 1;
        if (!(io & 1)) io--;
        g_is64 = (io >= 1 && bw[io] == 0) ? 1 : 0;
    }
}

// ---------------------------------------------------------------------------
// K1: fused MLP + x2 + sorted-segment partial sums via HMMA m16n8k16.
// 16 rows per warp group, double-buffered cp.async x staging.
// fc1 C-frags map directly to fc2 A-frags. fc1 A-frags are KEPT in registers
// and reused by the epilogue (no stage re-read). x2 stores go through a
// conflict-free fp16 smem transpose tile -> coalesced STG.128.
// ---------------------------------------------------------------------------
__global__ void __launch_bounds__(160, 2) k_mlp(
    const float* __restrict__ x, const int* __restrict__ bw,
    const float* __restrict__ fc1w, const float* __restrict__ fc1b,
    const float* __restrict__ fc2w, const float* __restrict__ fc2b,
    int N, int rpw)
{
    extern __shared__ char sm_[];
    uint2* w1f = (uint2*)sm_;                 // 1024 frags: [kt*4+nt][lane]
    uint2* w2f = w1f + 1024;                  // 1024 frags: [kt2*16+nt][lane]
    float* xs_all = (float*)(w2f + 1024);     // 5 warps * 2 bufs * 16 * 132 floats
    __half* x2s_all = (__half*)(xs_all + 5 * 2 * 16 * XS_STRIDE);  // 5 * 16 * 72 halves

    int tid = threadIdx.x;
    // Build weight fragments (B-frag layout, col-major B = W[n][k])
    for (int e = tid; e < 1024; e += 160) {
        int tile = e >> 5, ln = e & 31;
        int gg = ln >> 2, mm = ln & 3;
        {   // fc1: tile = kt*4 + nt
            int kt = tile >> 2, nt = tile & 3;
            const float* wr = fc1w + (nt * 8 + gg) * 128 + kt * 16 + 2 * mm;
            w1f[e] = make_uint2(packh2(wr[0], wr[1]), packh2(wr[8], wr[9]));
        }
        {   // fc2: tile = kt2*16 + nt
            int kt2 = tile >> 4, nt = tile & 15;
            const float* wr = fc2w + (nt * 8 + gg) * 32 + kt2 * 16 + 2 * mm;
            w2f[e] = make_uint2(packh2(wr[0], wr[1]), packh2(wr[8], wr[9]));
        }
    }
    __syncthreads();

    int lane = tid & 31, wid = tid >> 5;
    int g = lane >> 2, m = lane & 3;
    const int BUFSZ = 16 * XS_STRIDE;
    float* xsb = xs_all + wid * (2 * BUFSZ);
    __half* x2w = x2s_all + wid * (16 * X2S_STRIDE);

    int warp = blockIdx.x * 5 + wid;
    long long r0l = (long long)warp * rpw;
    if (r0l >= N) return;
    int rs = (int)r0l;
    int re = min(N, rs + rpw);

    bool is64 = (g_is64 != 0);
    float b1v[8];
    #pragma unroll
    for (int nt = 0; nt < 4; nt++) {
        float2 t = *(const float2*)&fc1b[nt * 8 + 2 * m];
        b1v[nt * 2] = t.x; b1v[nt * 2 + 1] = t.y;
    }

    float sacc[32];
    #pragma unroll
    for (int i = 0; i < 32; i++) sacc[i] = 0.0f;
    int cur_b = -1, cnt = 0;

    // prologue: group 0 -> buf 0
    #pragma unroll
    for (int q = 0; q < 16; q++) {
        int rr = rs + q; if (rr >= re) rr = re - 1;
        cpa16(&xsb[q * XS_STRIDE + lane * 4], &x[(size_t)rr * D + lane * 4]);
    }
    CP_COMMIT();

    int buf = 0;
    for (int r0 = rs; r0 < re; r0 += 16) {
        // issue next group into other buffer, then wait for current
        if (r0 + 16 < re) {
            float* nb = xsb + (buf ^ 1) * BUFSZ;
            #pragma unroll
            for (int q = 0; q < 16; q++) {
                int rr = r0 + 16 + q; if (rr >= re) rr = re - 1;
                cpa16(&nb[q * XS_STRIDE + lane * 4], &x[(size_t)rr * D + lane * 4]);
            }
            CP_COMMIT();
            CP_WAIT1();
        } else {
            CP_WAIT0();
        }
        __syncwarp();
        const float* xs = xsb + buf * BUFSZ;
        buf ^= 1;

        // batch ids (lanes 0..15 hold row lane's id)
        int mybat = 0;
        if (lane < 16) {
            int rr = r0 + lane; if (rr >= re) rr = re - 1;
            mybat = is64 ? bw[2 * rr] : bw[rr];
        }
        int nvalid = min(16, re - r0);
        int b_first = __shfl_sync(0xffffffffu, mybat, 0);
        int b_last  = __shfl_sync(0xffffffffu, mybat, nvalid - 1);
        bool mixed = (b_first != b_last);     // sorted => ends equal <=> uniform

        if ((mixed || b_first != cur_b) && cnt > 0) {
            #pragma unroll
            for (int i = 0; i < 32; i++) {
                sacc[i] += __shfl_xor_sync(0xffffffffu, sacc[i], 4);
                sacc[i] += __shfl_xor_sync(0xffffffffu, sacc[i], 8);
                sacc[i] += __shfl_xor_sync(0xffffffffu, sacc[i], 16);
            }
            if (lane < 4) {
                #pragma unroll
                for (int nt = 0; nt < 16; nt++) {
                    atomicAdd(&g_sums[cur_b * D + nt * 8 + 2 * lane],     sacc[nt * 2]);
                    atomicAdd(&g_sums[cur_b * D + nt * 8 + 2 * lane + 1], sacc[nt * 2 + 1]);
                }
            }
            if (lane == 0) atomicAdd(&g_cnt[cur_b], (float)cnt);
            #pragma unroll
            for (int i = 0; i < 32; i++) sacc[i] = 0.0f;
            cnt = 0;
        }
        if (!mixed) { cur_b = b_first; cnt += nvalid; }
        else        { cur_b = -1; }

        // --- fc1: C1[nt] = X @ W1^T; A-frags retained for the epilogue ---
        float C1[4][4];
        #pragma unroll
        for (int nt = 0; nt < 4; nt++)
            #pragma unroll
            for (int i = 0; i < 4; i++) C1[nt][i] = 0.0f;

        unsigned Af[8][4];
        #pragma unroll
        for (int kt = 0; kt < 8; kt++) {
            const float* xb = xs + kt * 16 + 2 * m;
            float2 p0 = *(const float2*)&xb[g * XS_STRIDE];
            float2 p1 = *(const float2*)&xb[(g + 8) * XS_STRIDE];
            float2 p2 = *(const float2*)&xb[g * XS_STRIDE + 8];
            float2 p3 = *(const float2*)&xb[(g + 8) * XS_STRIDE + 8];
            Af[kt][0] = packh2(p0.x, p0.y);
            Af[kt][1] = packh2(p1.x, p1.y);
            Af[kt][2] = packh2(p2.x, p2.y);
            Af[kt][3] = packh2(p3.x, p3.y);
            #pragma unroll
            for (int nt = 0; nt < 4; nt++) {
                uint2 bf = w1f[(kt * 4 + nt) * 32 + lane];
                unsigned B[2] = { bf.x, bf.y };
                mma16816(C1[nt], Af[kt], B);
            }
        }

        // --- bias + ReLU + direct C->A repack for fc2 ---
        unsigned A2[2][4];
        #pragma unroll
        for (int kt2 = 0; kt2 < 2; kt2++) {
            int nta = 2 * kt2, ntb = 2 * kt2 + 1;
            float ha0 = fmaxf(C1[nta][0] + b1v[nta * 2],     0.0f);
            float ha1 = fmaxf(C1[nta][1] + b1v[nta * 2 + 1], 0.0f);
            float ha2 = fmaxf(C1[nta][2] + b1v[nta * 2],     0.0f);
            float ha3 = fmaxf(C1[nta][3] + b1v[nta * 2 + 1], 0.0f);
            float hb0 = fmaxf(C1[ntb][0] + b1v[ntb * 2],     0.0f);
            float hb1 = fmaxf(C1[ntb][1] + b1v[ntb * 2 + 1], 0.0f);
            float hb2 = fmaxf(C1[ntb][2] + b1v[ntb * 2],     0.0f);
            float hb3 = fmaxf(C1[ntb][3] + b1v[ntb * 2 + 1], 0.0f);
            A2[kt2][0] = packh2(ha0, ha1);
            A2[kt2][1] = packh2(ha2, ha3);
            A2[kt2][2] = packh2(hb0, hb1);
            A2[kt2][3] = packh2(hb2, hb3);
        }

        // --- fc2 (two halves of 8 n-tiles) + epilogue (x from Af regs) ---
        bool vg  = (r0 + g)     < re;
        bool vg8 = (r0 + g + 8) < re;
        int bg = 0, bg8 = 0;
        if (mixed) {
            bg  = __shfl_sync(0xffffffffu, mybat, g);
            bg8 = __shfl_sync(0xffffffffu, mybat, g + 8);
        }

        #pragma unroll
        for (int hf = 0; hf < 2; hf++) {
            float C2[8][4];
            #pragma unroll
            for (int nn = 0; nn < 8; nn++) {
                int nt = hf * 8 + nn;
                float2 b2 = *(const float2*)&fc2b[nt * 8 + 2 * m];
                C2[nn][0] = b2.x; C2[nn][1] = b2.y;
                C2[nn][2] = b2.x; C2[nn][3] = b2.y;
                #pragma unroll
                for (int kt2 = 0; kt2 < 2; kt2++) {
                    uint2 bf = w2f[(kt2 * 16 + nt) * 32 + lane];
                    unsigned B[2] = { bf.x, bf.y };
                    mma16816(C2[nn], A2[kt2], B);
                }
            }
            #pragma unroll
            for (int nn = 0; nn < 8; nn++) {
                int nt = hf * 8 + nn;
                int dim = nt * 8 + 2 * m;      // global dim
                int ld  = nn * 8 + 2 * m;      // dim within this hf's 64-dim slab
                float a0 = ftanh(C2[nn][0]), a1 = ftanh(C2[nn][1]);
                float a2 = ftanh(C2[nn][2]), a3 = ftanh(C2[nn][3]);
                // x for this (nt, m) comes straight from the fc1 A-fragments:
                // nt even: dims 16kt+2m  -> Af[kt][0/1]; nt odd: +8 -> Af[kt][2/3]
                int kt = nt >> 1;
                int odd = nt & 1;
                float2 xg  = upkh2(Af[kt][odd ? 2 : 0]);
                float2 xg8 = upkh2(Af[kt][odd ? 3 : 1]);
                float v0 = fmaf(a0, xg.x,  xg.x);
                float v1 = fmaf(a1, xg.y,  xg.y);
                float v2 = fmaf(a2, xg8.x, xg8.x);
                float v3 = fmaf(a3, xg8.y, xg8.y);
                // conflict-free STS into the transpose tile
                *(__half2*)&x2w[g * X2S_STRIDE + ld]       = __floats2half2_rn(v0, v1);
                *(__half2*)&x2w[(g + 8) * X2S_STRIDE + ld] = __floats2half2_rn(v2, v3);
                if (!mixed) {
                    sacc[nt * 2]     += (vg ? v0 : 0.0f) + (vg8 ? v2 : 0.0f);
                    sacc[nt * 2 + 1] += (vg ? v1 : 0.0f) + (vg8 ? v3 : 0.0f);
                } else {
                    if (vg) {
                        atomicAdd(&g_sums[bg * D + dim],     v0);
                        atomicAdd(&g_sums[bg * D + dim + 1], v1);
                    }
                    if (vg8) {
                        atomicAdd(&g_sums[bg8 * D + dim],     v2);
                        atomicAdd(&g_sums[bg8 * D + dim + 1], v3);
                    }
                }
            }
            __syncwarp();
            // coalesced flush: 4 x STG.128, each 32 lanes x 16B over 4 rows
            #pragma unroll
            for (int it = 0; it < 4; it++) {
                int lrow = it * 4 + (lane >> 3);
                int chunk = lane & 7;
                int rr = r0 + lrow;
                if (rr < re) {
                    float4 v = *(const float4*)&x2w[lrow * X2S_STRIDE + chunk * 8];
                    *(float4*)&g_x2h[(size_t)rr * D + hf * 64 + chunk * 8] = v;
                }
            }
            if (hf == 0) __syncwarp();   // tile reused by hf=1 STS
        }
        if (mixed && lane < nvalid) atomicAdd(&g_cnt[mybat], 1.0f);
    }

    // final flush
    if (cnt > 0) {
        #pragma unroll
        for (int i = 0; i < 32; i++) {
            sacc[i] += __shfl_xor_sync(0xffffffffu, sacc[i], 4);
            sacc[i] += __shfl_xor_sync(0xffffffffu, sacc[i], 8);
            sacc[i] += __shfl_xor_sync(0xffffffffu, sacc[i], 16);
        }
        if (lane < 4) {
            #pragma unroll
            for (int nt = 0; nt < 16; nt++) {
                atomicAdd(&g_sums[cur_b * D + nt * 8 + 2 * lane],     sacc[nt * 2]);
                atomicAdd(&g_sums[cur_b * D + nt * 8 + 2 * lane + 1], sacc[nt * 2 + 1]);
            }
        }
        if (lane == 0) atomicAdd(&g_cnt[cur_b], (float)cnt);
    }
}

// ---------------------------------------------------------------------------
// K2: tg[b] = tanh( (sums[b]/max(cnt,1)) @ Wm ).  One block per segment.
// ---------------------------------------------------------------------------
__global__ void k_global(const float* __restrict__ Wm, int B) {
    int b = blockIdx.x, t = threadIdx.x;
    __shared__ float ms[128];
    float c = fmaxf(g_cnt[b], 1.0f);
    ms[t] = g_sums[b * D + t] / c;
    __syncthreads();
    float acc = 0.0f;
    #pragma unroll 16
    for (int k = 0; k < 128; k++) acc = fmaf(ms[k], Wm[k * D + t], acc);
    g_tg[b * D + t] = ftanh(acc);
}

// ---------------------------------------------------------------------------
// K3: coefs = sigmoid(<x2, tg[batch]>); out = segment_sum(coef * x2).
// Warp-per-row, 8-row groups, uniform fast path. x2 kept as raw half2 pairs
// (16 regs vs 32) to raise occupancy; transient unpack at use.
// ---------------------------------------------------------------------------
__global__ void __launch_bounds__(256, 5) k_out(
    const int* __restrict__ bw, float* __restrict__ out, int N, int rpw)
{
    int tid = threadIdx.x, lane = tid & 31;
    int warp = blockIdx.x * (blockDim.x >> 5) + (tid >> 5);
    long long r0l = (long long)warp * rpw;
    if (r0l >= N) return;
    int rs = (int)r0l;
    int re = min(N, rs + rpw);

    bool is64 = (g_is64 != 0);
    float4 acc = make_float4(0.f, 0.f, 0.f, 0.f);
    float4 tgv = make_float4(0.f, 0.f, 0.f, 0.f);
    int cur_b = -1;

    for (int r0 = rs; r0 < re; r0 += 8) {
        int m = min(8, re - r0);
        uint2 xh[8]; int bb[8];
        #pragma unroll
        for (int q = 0; q < 8; q++) {
            int rr = r0 + q; if (rr >= re) rr = re - 1;
            bb[q] = is64 ? bw[2 * rr] : bw[rr];
            xh[q] = __ldcs((const uint2*)&g_x2h[(size_t)rr * D + lane * 4]);
        }

        bool uni = (m == 8) & (bb[0] == cur_b) & (bb[7] == cur_b);
        if (uni) {
            float s[8];
            #pragma unroll
            for (int q = 0; q < 8; q++) {
                float2 f0 = upkh2(xh[q].x);
                float2 f1 = upkh2(xh[q].y);
                s[q] = fmaf(f0.x, tgv.x, fmaf(f0.y, tgv.y,
                       fmaf(f1.x, tgv.z, f1.y * tgv.w)));
            }
            #pragma unroll
            for (int off = 16; off >= 1; off >>= 1) {
                #pragma unroll
                for (int q = 0; q < 8; q++)
                    s[q] += __shfl_xor_sync(0xffffffffu, s[q], off);
            }
            #pragma unroll
            for (int q = 0; q < 8; q++) {
                float coef = fsigmoid(s[q]);
                float2 f0 = upkh2(xh[q].x);
                float2 f1 = upkh2(xh[q].y);
                acc.x = fmaf(coef, f0.x, acc.x);
                acc.y = fmaf(coef, f0.y, acc.y);
                acc.z = fmaf(coef, f1.x, acc.z);
                acc.w = fmaf(coef, f1.y, acc.w);
            }
        } else {
            #pragma unroll
            for (int q = 0; q < 8; q++) {
                if (q >= m) break;
                int b = bb[q];
                if (b != cur_b) {
                    if (cur_b >= 0) {
                        float* dst = &out[cur_b * D + lane * 4];
                        atomicAdd(dst + 0, acc.x);
                        atomicAdd(dst + 1, acc.y);
                        atomicAdd(dst + 2, acc.z);
                        atomicAdd(dst + 3, acc.w);
                    }
                    acc = make_float4(0.f, 0.f, 0.f, 0.f);
                    cur_b = b;
                    tgv = ((const float4*)g_tg)[b * 32 + lane];
                }
                float2 f0 = upkh2(xh[q].x);
                float2 f1 = upkh2(xh[q].y);
                float s = fmaf(f0.x, tgv.x, fmaf(f0.y, tgv.y,
                          fmaf(f1.x, tgv.z, f1.y * tgv.w)));
                #pragma unroll
                for (int off = 16; off >= 1; off >>= 1)
                    s += __shfl_xor_sync(0xffffffffu, s, off);
                float coef = fsigmoid(s);
                acc.x = fmaf(coef, f0.x, acc.x);
                acc.y = fmaf(coef, f0.y, acc.y);
                acc.z = fmaf(coef, f1.x, acc.z);
                acc.w = fmaf(coef, f1.y, acc.w);
            }
        }
    }
    if (cur_b >= 0) {
        float* dst = &out[cur_b * D + lane * 4];
        atomicAdd(dst + 0, acc.x);
        atomicAdd(dst + 1, acc.y);
        atomicAdd(dst + 2, acc.z);
        atomicAdd(dst + 3, acc.w);
    }
}

// ---------------------------------------------------------------------------
// Inputs (metadata order): x, batch, [size], Wm, fc1_w, fc1_b, fc2_w, fc2_b
// ---------------------------------------------------------------------------
extern "C" void kernel_launch(void* const* d_in, const int* in_sizes, int n_in,
                              void* d_out, int out_size)
{
    const float* x  = (const float*)d_in[0];
    const int*   bw = (const int*)d_in[1];
    int base = 2;
    if (n_in >= 8 && in_sizes[2] < 64) base = 3;   // scalar 'size' input present
    const float* Wm   = (const float*)d_in[base + 0];
    const float* fc1w = (const float*)d_in[base + 1];
    const float* fc1b = (const float*)d_in[base + 2];
    const float* fc2w = (const float*)d_in[base + 3];
    const float* fc2b = (const float*)d_in[base + 4];

    int N = in_sizes[0] / D;
    if (N > NMAX) N = NMAX;
    int B = out_size / D;
    if (B > BMAX) B = BMAX;
    float* out = (float*)d_out;

    k_init<<<256, 256>>>(out, out_size, B, bw, N);

    // k_mlp smem: 16KB frags + 5*2*16*132*4B x-stage + 5*16*72*2B x2-stage
    const size_t MSMEM = 2048 * sizeof(uint2)
                       + (size_t)5 * 2 * 16 * XS_STRIDE * sizeof(float)
                       + (size_t)5 * 16 * X2S_STRIDE * sizeof(__half);  // 112384 B
    static int attr_done = 0;
    if (!attr_done) {
        cudaFuncSetAttribute(k_mlp, cudaFuncAttributeMaxDynamicSharedMemorySize,
                             (int)MSMEM);
        attr_done = 1;
    }
    const int RPW = 344;   // 291 blocks <= 296 resident slots (148 SMs x 2)
    int warps = (N + RPW - 1) / RPW;
    int mblocks = (warps + 4) / 5;
    k_mlp<<<mblocks, 160, MSMEM>>>(x, bw, fc1w, fc1b, fc2w, fc2b, N, RPW);

    k_global<<<B, 128>>>(Wm, B);

    const int RPW_OUT = 64;
    int owarps = (N + RPW_OUT - 1) / RPW_OUT;
    int oblocks = (owarps + 7) / 8;
    k_out<<<oblocks, 256>>>(bw, out, N, RPW_OUT);
}

// round 13
// speedup vs baseline: 1.4956x; 1.4956x over previous
#include <cuda_runtime.h>
#include <cuda_fp16.h>

#define D 128
#define NMAX 500000
#define BMAX 4096
#define XS_STRIDE 132   // padded floats per staged row (bank spread)
#define X2S_STRIDE 72   // halves per staged x2 row (144B; conflict-free STS)

// Scratch (static __device__ globals — no allocation anywhere)
__device__ __align__(16) __half g_x2h[(size_t)NMAX * D];  // 128 MB fp16 x2
__device__ float g_sums[BMAX * D];
__device__ float g_cnt[BMAX];
__device__ float g_tg[BMAX * D];
__device__ int   g_is64;

__device__ __forceinline__ float ftanh(float v) {
    float r;
    asm("tanh.approx.f32 %0,%1;" : "=f"(r) : "f"(v));
    return r;
}
__device__ __forceinline__ float fsigmoid(float v) {
    float r;
    asm("tanh.approx.f32 %0,%1;" : "=f"(r) : "f"(0.5f * v));
    return fmaf(0.5f, r, 0.5f);
}

__device__ __forceinline__ void cpa16(const void* smem_dst, const void* gmem_src) {
    unsigned s = (unsigned)__cvta_generic_to_shared(smem_dst);
    asm volatile("cp.async.cg.shared.global [%0],[%1],16;" :: "r"(s), "l"(gmem_src));
}
#define CP_COMMIT() asm volatile("cp.async.commit_group;")
#define CP_WAIT1()  asm volatile("cp.async.wait_group 1;")
#define CP_WAIT0()  asm volatile("cp.async.wait_group 0;")

// m16n8k16 row.col f32 += f16*f16
__device__ __forceinline__ void mma16816(float c[4], const unsigned a[4], const unsigned b[2]) {
    asm volatile(
        "mma.sync.aligned.m16n8k16.row.col.f32.f16.f16.f32 "
        "{%0,%1,%2,%3},{%4,%5,%6,%7},{%8,%9},{%0,%1,%2,%3};"
        : "+f"(c[0]), "+f"(c[1]), "+f"(c[2]), "+f"(c[3])
        : "r"(a[0]), "r"(a[1]), "r"(a[2]), "r"(a[3]), "r"(b[0]), "r"(b[1]));
}

__device__ __forceinline__ unsigned packh2(float a, float b) {
    __half2 h = __floats2half2_rn(a, b);
    return *(unsigned*)&h;
}
__device__ __forceinline__ float2 upkh2(unsigned u) {
    return __half22float2(*(__half2*)&u);
}

// ---------------------------------------------------------------------------
// K0: zero accumulators + output; detect batch element width (int64 vs int32).
// ---------------------------------------------------------------------------
__global__ void k_init(float* out, int outn, int B, const int* bw, int N) {
    int i = blockIdx.x * blockDim.x + threadIdx.x;
    int stride = gridDim.x * blockDim.x;
    for (int k = i; k < B * D; k += stride) g_sums[k] = 0.0f;
    for (int k = i; k < B; k += stride) g_cnt[k] = 0.0f;
    for (int k = i; k < outn; k += stride) out[k] = 0.0f;
    if (i == 0) {
        int io = N - 1;
        if (!(io & 1)) io--;
        g_is64 = (io >= 1 && bw[io] == 0) ? 1 : 0;
    }
}

// ---------------------------------------------------------------------------
// K1: fused MLP + x2 + sorted-segment partial sums via HMMA m16n8k16.
// 16 rows per warp group, double-buffered cp.async x staging.
// fc1 C-frags map directly to fc2 A-frags. Epilogue x re-read from the fp32
// stage (register-retention variant spilled — R12). fc2 bias cached in smem.
// x2 stores via conflict-free fp16 smem transpose tile -> coalesced STG.128.
// ---------------------------------------------------------------------------
__global__ void __launch_bounds__(160, 2) k_mlp(
    const float* __restrict__ x, const int* __restrict__ bw,
    const float* __restrict__ fc1w, const float* __restrict__ fc1b,
    const float* __restrict__ fc2w, const float* __restrict__ fc2b,
    int N, int rpw)
{
    extern __shared__ char sm_[];
    uint2* w1f = (uint2*)sm_;                 // 1024 frags: [kt*4+nt][lane]
    uint2* w2f = w1f + 1024;                  // 1024 frags: [kt2*16+nt][lane]
    float* xs_all = (float*)(w2f + 1024);     // 5 warps * 2 bufs * 16 * 132 floats
    __half* x2s_all = (__half*)(xs_all + 5 * 2 * 16 * XS_STRIDE);  // 5 * 16 * 72 halves
    float* b2s = (float*)(x2s_all + 5 * 16 * X2S_STRIDE);          // 128 floats

    int tid = threadIdx.x;
    // Build weight fragments (B-frag layout, col-major B = W[n][k])
    for (int e = tid; e < 1024; e += 160) {
        int tile = e >> 5, ln = e & 31;
        int gg = ln >> 2, mm = ln & 3;
        {   // fc1: tile = kt*4 + nt
            int kt = tile >> 2, nt = tile & 3;
            const float* wr = fc1w + (nt * 8 + gg) * 128 + kt * 16 + 2 * mm;
            w1f[e] = make_uint2(packh2(wr[0], wr[1]), packh2(wr[8], wr[9]));
        }
        {   // fc2: tile = kt2*16 + nt
            int kt2 = tile >> 4, nt = tile & 15;
            const float* wr = fc2w + (nt * 8 + gg) * 32 + kt2 * 16 + 2 * mm;
            w2f[e] = make_uint2(packh2(wr[0], wr[1]), packh2(wr[8], wr[9]));
        }
    }
    if (tid < 128) b2s[tid] = fc2b[tid];
    __syncthreads();

    int lane = tid & 31, wid = tid >> 5;
    int g = lane >> 2, m = lane & 3;
    const int BUFSZ = 16 * XS_STRIDE;
    float* xsb = xs_all + wid * (2 * BUFSZ);
    __half* x2w = x2s_all + wid * (16 * X2S_STRIDE);

    int warp = blockIdx.x * 5 + wid;
    long long r0l = (long long)warp * rpw;
    if (r0l >= N) return;
    int rs = (int)r0l;
    int re = min(N, rs + rpw);

    bool is64 = (g_is64 != 0);
    float b1v[8];
    #pragma unroll
    for (int nt = 0; nt < 4; nt++) {
        float2 t = *(const float2*)&fc1b[nt * 8 + 2 * m];
        b1v[nt * 2] = t.x; b1v[nt * 2 + 1] = t.y;
    }

    float sacc[32];
    #pragma unroll
    for (int i = 0; i < 32; i++) sacc[i] = 0.0f;
    int cur_b = -1, cnt = 0;

    // prologue: group 0 -> buf 0
    #pragma unroll
    for (int q = 0; q < 16; q++) {
        int rr = rs + q; if (rr >= re) rr = re - 1;
        cpa16(&xsb[q * XS_STRIDE + lane * 4], &x[(size_t)rr * D + lane * 4]);
    }
    CP_COMMIT();

    int buf = 0;
    for (int r0 = rs; r0 < re; r0 += 16) {
        // issue next group into other buffer, then wait for current
        if (r0 + 16 < re) {
            float* nb = xsb + (buf ^ 1) * BUFSZ;
            #pragma unroll
            for (int q = 0; q < 16; q++) {
                int rr = r0 + 16 + q; if (rr >= re) rr = re - 1;
                cpa16(&nb[q * XS_STRIDE + lane * 4], &x[(size_t)rr * D + lane * 4]);
            }
            CP_COMMIT();
            CP_WAIT1();
        } else {
            CP_WAIT0();
        }
        __syncwarp();
        const float* xs = xsb + buf * BUFSZ;
        buf ^= 1;

        // batch ids (lanes 0..15 hold row lane's id)
        int mybat = 0;
        if (lane < 16) {
            int rr = r0 + lane; if (rr >= re) rr = re - 1;
            mybat = is64 ? bw[2 * rr] : bw[rr];
        }
        int nvalid = min(16, re - r0);
        int b_first = __shfl_sync(0xffffffffu, mybat, 0);
        int b_last  = __shfl_sync(0xffffffffu, mybat, nvalid - 1);
        bool mixed = (b_first != b_last);     // sorted => ends equal <=> uniform

        if ((mixed || b_first != cur_b) && cnt > 0) {
            #pragma unroll
            for (int i = 0; i < 32; i++) {
                sacc[i] += __shfl_xor_sync(0xffffffffu, sacc[i], 4);
                sacc[i] += __shfl_xor_sync(0xffffffffu, sacc[i], 8);
                sacc[i] += __shfl_xor_sync(0xffffffffu, sacc[i], 16);
            }
            if (lane < 4) {
                #pragma unroll
                for (int nt = 0; nt < 16; nt++) {
                    atomicAdd(&g_sums[cur_b * D + nt * 8 + 2 * lane],     sacc[nt * 2]);
                    atomicAdd(&g_sums[cur_b * D + nt * 8 + 2 * lane + 1], sacc[nt * 2 + 1]);
                }
            }
            if (lane == 0) atomicAdd(&g_cnt[cur_b], (float)cnt);
            #pragma unroll
            for (int i = 0; i < 32; i++) sacc[i] = 0.0f;
            cnt = 0;
        }
        if (!mixed) { cur_b = b_first; cnt += nvalid; }
        else        { cur_b = -1; }

        // --- fc1: C1[nt] = X @ W1^T (tile nt) ---
        float C1[4][4];
        #pragma unroll
        for (int nt = 0; nt < 4; nt++)
            #pragma unroll
            for (int i = 0; i < 4; i++) C1[nt][i] = 0.0f;

        #pragma unroll
        for (int kt = 0; kt < 8; kt++) {
            const float* xb = xs + kt * 16 + 2 * m;
            float2 p0 = *(const float2*)&xb[g * XS_STRIDE];
            float2 p1 = *(const float2*)&xb[(g + 8) * XS_STRIDE];
            float2 p2 = *(const float2*)&xb[g * XS_STRIDE + 8];
            float2 p3 = *(const float2*)&xb[(g + 8) * XS_STRIDE + 8];
            unsigned A[4];
            A[0] = packh2(p0.x, p0.y);
            A[1] = packh2(p1.x, p1.y);
            A[2] = packh2(p2.x, p2.y);
            A[3] = packh2(p3.x, p3.y);
            #pragma unroll
            for (int nt = 0; nt < 4; nt++) {
                uint2 bf = w1f[(kt * 4 + nt) * 32 + lane];
                unsigned B[2] = { bf.x, bf.y };
                mma16816(C1[nt], A, B);
            }
        }

        // --- bias + ReLU + direct C->A repack for fc2 ---
        unsigned A2[2][4];
        #pragma unroll
        for (int kt2 = 0; kt2 < 2; kt2++) {
            int nta = 2 * kt2, ntb = 2 * kt2 + 1;
            float ha0 = fmaxf(C1[nta][0] + b1v[nta * 2],     0.0f);
            float ha1 = fmaxf(C1[nta][1] + b1v[nta * 2 + 1], 0.0f);
            float ha2 = fmaxf(C1[nta][2] + b1v[nta * 2],     0.0f);
            float ha3 = fmaxf(C1[nta][3] + b1v[nta * 2 + 1], 0.0f);
            float hb0 = fmaxf(C1[ntb][0] + b1v[ntb * 2],     0.0f);
            float hb1 = fmaxf(C1[ntb][1] + b1v[ntb * 2 + 1], 0.0f);
            float hb2 = fmaxf(C1[ntb][2] + b1v[ntb * 2],     0.0f);
            float hb3 = fmaxf(C1[ntb][3] + b1v[ntb * 2 + 1], 0.0f);
            A2[kt2][0] = packh2(ha0, ha1);
            A2[kt2][1] = packh2(ha2, ha3);
            A2[kt2][2] = packh2(hb0, hb1);
            A2[kt2][3] = packh2(hb2, hb3);
        }

        // --- fc2 (two halves of 8 n-tiles) + epilogue ---
        bool vg  = (r0 + g)     < re;
        bool vg8 = (r0 + g + 8) < re;
        int bg = 0, bg8 = 0;
        if (mixed) {
            bg  = __shfl_sync(0xffffffffu, mybat, g);
            bg8 = __shfl_sync(0xffffffffu, mybat, g + 8);
        }

        #pragma unroll
        for (int hf = 0; hf < 2; hf++) {
            float C2[8][4];
            #pragma unroll
            for (int nn = 0; nn < 8; nn++) {
                int nt = hf * 8 + nn;
                float2 b2 = *(const float2*)&b2s[nt * 8 + 2 * m];
                C2[nn][0] = b2.x; C2[nn][1] = b2.y;
                C2[nn][2] = b2.x; C2[nn][3] = b2.y;
                #pragma unroll
                for (int kt2 = 0; kt2 < 2; kt2++) {
                    uint2 bf = w2f[(kt2 * 16 + nt) * 32 + lane];
                    unsigned B[2] = { bf.x, bf.y };
                    mma16816(C2[nn], A2[kt2], B);
                }
            }
            #pragma unroll
            for (int nn = 0; nn < 8; nn++) {
                int nt = hf * 8 + nn;
                int dim = nt * 8 + 2 * m;      // global dim
                int ld  = nn * 8 + 2 * m;      // dim within this hf's 64-dim slab
                float a0 = ftanh(C2[nn][0]), a1 = ftanh(C2[nn][1]);
                float a2 = ftanh(C2[nn][2]), a3 = ftanh(C2[nn][3]);
                float2 xg  = *(const float2*)&xs[g * XS_STRIDE + dim];
                float2 xg8 = *(const float2*)&xs[(g + 8) * XS_STRIDE + dim];
                float v0 = fmaf(a0, xg.x,  xg.x);
                float v1 = fmaf(a1, xg.y,  xg.y);
                float v2 = fmaf(a2, xg8.x, xg8.x);
                float v3 = fmaf(a3, xg8.y, xg8.y);
                // conflict-free STS into the transpose tile
                *(__half2*)&x2w[g * X2S_STRIDE + ld]       = __floats2half2_rn(v0, v1);
                *(__half2*)&x2w[(g + 8) * X2S_STRIDE + ld] = __floats2half2_rn(v2, v3);
                if (!mixed) {
                    sacc[nt * 2]     += (vg ? v0 : 0.0f) + (vg8 ? v2 : 0.0f);
                    sacc[nt * 2 + 1] += (vg ? v1 : 0.0f) + (vg8 ? v3 : 0.0f);
                } else {
                    if (vg) {
                        atomicAdd(&g_sums[bg * D + dim],     v0);
                        atomicAdd(&g_sums[bg * D + dim + 1], v1);
                    }
                    if (vg8) {
                        atomicAdd(&g_sums[bg8 * D + dim],     v2);
                        atomicAdd(&g_sums[bg8 * D + dim + 1], v3);
                    }
                }
            }
            __syncwarp();
            // coalesced flush: 4 x STG.128, each 32 lanes x 16B over 4 rows
            #pragma unroll
            for (int it = 0; it < 4; it++) {
                int lrow = it * 4 + (lane >> 3);
                int chunk = lane & 7;
                int rr = r0 + lrow;
                if (rr < re) {
                    float4 v = *(const float4*)&x2w[lrow * X2S_STRIDE + chunk * 8];
                    *(float4*)&g_x2h[(size_t)rr * D + hf * 64 + chunk * 8] = v;
                }
            }
            if (hf == 0) __syncwarp();   // tile reused by hf=1 STS
        }
        if (mixed && lane < nvalid) atomicAdd(&g_cnt[mybat], 1.0f);
    }

    // final flush
    if (cnt > 0) {
        #pragma unroll
        for (int i = 0; i < 32; i++) {
            sacc[i] += __shfl_xor_sync(0xffffffffu, sacc[i], 4);
            sacc[i] += __shfl_xor_sync(0xffffffffu, sacc[i], 8);
            sacc[i] += __shfl_xor_sync(0xffffffffu, sacc[i], 16);
        }
        if (lane < 4) {
            #pragma unroll
            for (int nt = 0; nt < 16; nt++) {
                atomicAdd(&g_sums[cur_b * D + nt * 8 + 2 * lane],     sacc[nt * 2]);
                atomicAdd(&g_sums[cur_b * D + nt * 8 + 2 * lane + 1], sacc[nt * 2 + 1]);
            }
        }
        if (lane == 0) atomicAdd(&g_cnt[cur_b], (float)cnt);
    }
}

// ---------------------------------------------------------------------------
// K2: tg[b] = tanh( (sums[b]/max(cnt,1)) @ Wm ).  One block per segment.
// ---------------------------------------------------------------------------
__global__ void k_global(const float* __restrict__ Wm, int B) {
    int b = blockIdx.x, t = threadIdx.x;
    __shared__ float ms[128];
    float c = fmaxf(g_cnt[b], 1.0f);
    ms[t] = g_sums[b * D + t] / c;
    __syncthreads();
    float acc = 0.0f;
    #pragma unroll 16
    for (int k = 0; k < 128; k++) acc = fmaf(ms[k], Wm[k * D + t], acc);
    g_tg[b * D + t] = ftanh(acc);
}

// ---------------------------------------------------------------------------
// K3: coefs = sigmoid(<x2, tg[batch]>); out = segment_sum(coef * x2).
// Warp-per-row, 8-row groups, uniform fast path (R11 structure, 64 regs,
// NO launch-bounds cap — capping to 48 regs spilled in R12).
// ---------------------------------------------------------------------------
__global__ void __launch_bounds__(256) k_out(
    const int* __restrict__ bw, float* __restrict__ out, int N, int rpw)
{
    int tid = threadIdx.x, lane = tid & 31;
    int warp = blockIdx.x * (blockDim.x >> 5) + (tid >> 5);
    long long r0l = (long long)warp * rpw;
    if (r0l >= N) return;
    int rs = (int)r0l;
    int re = min(N, rs + rpw);

    bool is64 = (g_is64 != 0);
    float4 acc = make_float4(0.f, 0.f, 0.f, 0.f);
    float4 tgv = make_float4(0.f, 0.f, 0.f, 0.f);
    int cur_b = -1;

    for (int r0 = rs; r0 < re; r0 += 8) {
        int m = min(8, re - r0);
        float4 xv[8]; int bb[8];
        #pragma unroll
        for (int q = 0; q < 8; q++) {
            int rr = r0 + q; if (rr >= re) rr = re - 1;
            bb[q] = is64 ? bw[2 * rr] : bw[rr];
            float2 u = __ldcs((const float2*)&g_x2h[(size_t)rr * D + lane * 4]);
            unsigned u0 = __float_as_uint(u.x), u1 = __float_as_uint(u.y);
            float2 f0 = __half22float2(*(__half2*)&u0);
            float2 f1 = __half22float2(*(__half2*)&u1);
            xv[q] = make_float4(f0.x, f0.y, f1.x, f1.y);
        }

        bool uni = (m == 8) & (bb[0] == cur_b) & (bb[7] == cur_b);
        if (uni) {
            float s[8];
            #pragma unroll
            for (int q = 0; q < 8; q++)
                s[q] = fmaf(xv[q].x, tgv.x, fmaf(xv[q].y, tgv.y,
                       fmaf(xv[q].z, tgv.z, xv[q].w * tgv.w)));
            #pragma unroll
            for (int off = 16; off >= 1; off >>= 1) {
                #pragma unroll
                for (int q = 0; q < 8; q++)
                    s[q] += __shfl_xor_sync(0xffffffffu, s[q], off);
            }
            #pragma unroll
            for (int q = 0; q < 8; q++) {
                float coef = fsigmoid(s[q]);
                acc.x = fmaf(coef, xv[q].x, acc.x);
                acc.y = fmaf(coef, xv[q].y, acc.y);
                acc.z = fmaf(coef, xv[q].z, acc.z);
                acc.w = fmaf(coef, xv[q].w, acc.w);
            }
        } else {
            #pragma unroll
            for (int q = 0; q < 8; q++) {
                if (q >= m) break;
                int b = bb[q];
                if (b != cur_b) {
                    if (cur_b >= 0) {
                        float* dst = &out[cur_b * D + lane * 4];
                        atomicAdd(dst + 0, acc.x);
                        atomicAdd(dst + 1, acc.y);
                        atomicAdd(dst + 2, acc.z);
                        atomicAdd(dst + 3, acc.w);
                    }
                    acc = make_float4(0.f, 0.f, 0.f, 0.f);
                    cur_b = b;
                    tgv = ((const float4*)g_tg)[b * 32 + lane];
                }
                float s = fmaf(xv[q].x, tgv.x, fmaf(xv[q].y, tgv.y,
                          fmaf(xv[q].z, tgv.z, xv[q].w * tgv.w)));
                #pragma unroll
                for (int off = 16; off >= 1; off >>= 1)
                    s += __shfl_xor_sync(0xffffffffu, s, off);
                float coef = fsigmoid(s);
                acc.x = fmaf(coef, xv[q].x, acc.x);
                acc.y = fmaf(coef, xv[q].y, acc.y);
                acc.z = fmaf(coef, xv[q].z, acc.z);
                acc.w = fmaf(coef, xv[q].w, acc.w);
            }
        }
    }
    if (cur_b >= 0) {
        float* dst = &out[cur_b * D + lane * 4];
        atomicAdd(dst + 0, acc.x);
        atomicAdd(dst + 1, acc.y);
        atomicAdd(dst + 2, acc.z);
        atomicAdd(dst + 3, acc.w);
    }
}

// ---------------------------------------------------------------------------
// Inputs (metadata order): x, batch, [size], Wm, fc1_w, fc1_b, fc2_w, fc2_b
// ---------------------------------------------------------------------------
extern "C" void kernel_launch(void* const* d_in, const int* in_sizes, int n_in,
                              void* d_out, int out_size)
{
    const float* x  = (const float*)d_in[0];
    const int*   bw = (const int*)d_in[1];
    int base = 2;
    if (n_in >= 8 && in_sizes[2] < 64) base = 3;   // scalar 'size' input present
    const float* Wm   = (const float*)d_in[base + 0];
    const float* fc1w = (const float*)d_in[base + 1];
    const float* fc1b = (const float*)d_in[base + 2];
    const float* fc2w = (const float*)d_in[base + 3];
    const float* fc2b = (const float*)d_in[base + 4];

    int N = in_sizes[0] / D;
    if (N > NMAX) N = NMAX;
    int B = out_size / D;
    if (B > BMAX) B = BMAX;
    float* out = (float*)d_out;

    k_init<<<256, 256>>>(out, out_size, B, bw, N);

    // k_mlp smem: 16KB frags + x-stage + x2-stage + 512B bias = 112896 B
    const size_t MSMEM = 2048 * sizeof(uint2)
                       + (size_t)5 * 2 * 16 * XS_STRIDE * sizeof(float)
                       + (size_t)5 * 16 * X2S_STRIDE * sizeof(__half)
                       + 128 * sizeof(float);
    static int attr_done = 0;
    if (!attr_done) {
        cudaFuncSetAttribute(k_mlp, cudaFuncAttributeMaxDynamicSharedMemorySize,
                             (int)MSMEM);
        attr_done = 1;
    }
    const int RPW = 344;   // 291 blocks <= 296 resident slots (148 SMs x 2)
    int warps = (N + RPW - 1) / RPW;
    int mblocks = (warps + 4) / 5;
    k_mlp<<<mblocks, 160, MSMEM>>>(x, bw, fc1w, fc1b, fc2w, fc2b, N, RPW);

    k_global<<<B, 128>>>(Wm, B);

    const int RPW_OUT = 64;
    int owarps = (N + RPW_OUT - 1) / RPW_OUT;
    int oblocks = (owarps + 7) / 8;
    k_out<<<oblocks, 256>>>(bw, out, N, RPW_OUT);
}